// round 1
// baseline (speedup 1.0000x reference)
#include <cuda_runtime.h>

#define NTHREADS 256

// Dimensions (fixed by the problem)
#define SDIM   3
#define LDIM   4
#define IDIM   3
#define TOT    7     // SDIM + LDIM
#define SUDIM  10    // TOT + IDIM
#define HIDL   64
#define HIDB   32
#define DT_F   0.01f

// Shared-memory weight layout offsets (floats)
#define OFF_A    0
#define OFF_BM   9
#define OFF_C    18
#define OFF_WZ   27
#define OFF_BZ   97
#define OFF_W1   104
#define OFF_B1   744
#define OFF_W2   808
#define OFF_B2   1064
#define OFF_WB1  1068
#define OFF_BB1  1644
#define OFF_WB2  1740
#define OFF_BB2  1836
#define W_TOTAL  1839

__device__ __forceinline__ float fast_tanh(float x) {
    float r;
    asm("tanh.approx.f32 %0, %1;" : "=f"(r) : "f"(x));
    return r;
}

// sigmoid(x) = 0.5 * (1 + tanh(x/2))
__device__ __forceinline__ float fast_sigmoid(float x) {
    return fmaf(0.5f, fast_tanh(0.5f * x), 0.5f);
}

__global__ void __launch_bounds__(NTHREADS)
phygru_kernel(const float* __restrict__ state,
              const float* __restrict__ u,
              const float* __restrict__ gA,  const float* __restrict__ gBm,
              const float* __restrict__ gC,  const float* __restrict__ gWz,
              const float* __restrict__ gbz, const float* __restrict__ gW1,
              const float* __restrict__ gb1, const float* __restrict__ gW2,
              const float* __restrict__ gb2, const float* __restrict__ gWb1,
              const float* __restrict__ gbb1,const float* __restrict__ gWb2,
              const float* __restrict__ gbb2,
              float* __restrict__ out_state,
              float* __restrict__ out_y,
              int B)
{
    __shared__ float w[W_TOTAL];

    // ---- Stage all weights into shared memory (broadcast-read later) ----
    {
        const float* srcs[13] = {gA, gBm, gC, gWz, gbz, gW1, gb1, gW2, gb2,
                                 gWb1, gbb1, gWb2, gbb2};
        const int    szs[13]  = {9, 9, 9, 70, 7, 640, 64, 256, 4, 576, 96, 96, 3};
        const int    offs[13] = {OFF_A, OFF_BM, OFF_C, OFF_WZ, OFF_BZ, OFF_W1,
                                 OFF_B1, OFF_W2, OFF_B2, OFF_WB1, OFF_BB1,
                                 OFF_WB2, OFF_BB2};
        #pragma unroll
        for (int a = 0; a < 13; a++) {
            const float* s = srcs[a];
            int n = szs[a], o = offs[a];
            for (int i = threadIdx.x; i < n; i += NTHREADS)
                w[o + i] = s[i];
        }
    }
    __syncthreads();

    int row = blockIdx.x * NTHREADS + threadIdx.x;
    if (row >= B) return;

    // ---- Load this row's inputs ----
    float st[TOT];
    {
        const float* sp = state + (size_t)row * TOT;
        #pragma unroll
        for (int i = 0; i < TOT; i++) st[i] = __ldg(sp + i);
    }
    float uu[IDIM];
    {
        const float* up = u + (size_t)row * IDIM;
        #pragma unroll
        for (int i = 0; i < IDIM; i++) uu[i] = __ldg(up + i);
    }
    float su[SUDIM];
    #pragma unroll
    for (int i = 0; i < TOT; i++) su[i] = st[i];
    #pragma unroll
    for (int i = 0; i < IDIM; i++) su[TOT + i] = uu[i];

    // ---- Physics: s_dot = A s + Bm u ; y_phys = C s ; s_phys_next = s + DT*s_dot
    float cand[TOT];
    float yph[SDIM];
    #pragma unroll
    for (int i = 0; i < SDIM; i++) {
        float d = 0.f;
        #pragma unroll
        for (int j = 0; j < SDIM; j++) d = fmaf(w[OFF_A + i * SDIM + j], st[j], d);
        #pragma unroll
        for (int j = 0; j < IDIM; j++) d = fmaf(w[OFF_BM + i * IDIM + j], uu[j], d);
        cand[i] = fmaf(DT_F, d, st[i]);

        float yp = 0.f;
        #pragma unroll
        for (int j = 0; j < SDIM; j++) yp = fmaf(w[OFF_C + i * SDIM + j], st[j], yp);
        yph[i] = yp;
    }

    // ---- Latent MLP: latent_dot = W2 tanh(W1 su + b1) + b2 (fused accumulation)
    float acc[LDIM];
    #pragma unroll
    for (int o = 0; o < LDIM; o++) acc[o] = w[OFF_B2 + o];
    #pragma unroll 8
    for (int j = 0; j < HIDL; j++) {
        float t = w[OFF_B1 + j];
        #pragma unroll
        for (int k = 0; k < SUDIM; k++)
            t = fmaf(w[OFF_W1 + j * SUDIM + k], su[k], t);
        float th = fast_tanh(t);
        #pragma unroll
        for (int o = 0; o < LDIM; o++)
            acc[o] = fmaf(w[OFF_W2 + o * HIDL + j], th, acc[o]);
    }
    #pragma unroll
    for (int o = 0; o < LDIM; o++)
        cand[SDIM + o] = fmaf(DT_F, acc[o], st[SDIM + o]);

    // ---- Gate: z = sigmoid(Wz su + bz); next = st + z*(cand - st) ----
    float* orow = out_state + (size_t)row * TOT;
    #pragma unroll
    for (int i = 0; i < TOT; i++) {
        float a = w[OFF_BZ + i];
        #pragma unroll
        for (int k = 0; k < SUDIM; k++)
            a = fmaf(w[OFF_WZ + i * SUDIM + k], su[k], a);
        float z = fast_sigmoid(a);
        orow[i] = fmaf(z, cand[i] - st[i], st[i]);
    }

    // ---- Residual branches: y = y_phys + Wb2 . tanh(Wb1 [s,u] + bb1) + bb2 ----
    float bin[SDIM + IDIM];
    #pragma unroll
    for (int i = 0; i < SDIM; i++) bin[i] = st[i];
    #pragma unroll
    for (int i = 0; i < IDIM; i++) bin[SDIM + i] = uu[i];

    float* yrow = out_y + (size_t)row * SDIM;
    #pragma unroll
    for (int k = 0; k < SDIM; k++) {
        float r = w[OFF_BB2 + k];
        #pragma unroll 8
        for (int j = 0; j < HIDB; j++) {
            float t = w[OFF_BB1 + k * HIDB + j];
            #pragma unroll
            for (int i = 0; i < SDIM + IDIM; i++)
                t = fmaf(w[OFF_WB1 + (k * HIDB + j) * (SDIM + IDIM) + i], bin[i], t);
            r = fmaf(fast_tanh(t), w[OFF_WB2 + k * HIDB + j], r);
        }
        yrow[k] = yph[k] + r;
    }
}

extern "C" void kernel_launch(void* const* d_in, const int* in_sizes, int n_in,
                              void* d_out, int out_size) {
    const float* state = (const float*)d_in[0];
    const float* u     = (const float*)d_in[1];
    const float* A     = (const float*)d_in[2];
    const float* Bm    = (const float*)d_in[3];
    const float* C     = (const float*)d_in[4];
    const float* Wz    = (const float*)d_in[5];
    const float* bz    = (const float*)d_in[6];
    const float* W1    = (const float*)d_in[7];
    const float* b1    = (const float*)d_in[8];
    const float* W2    = (const float*)d_in[9];
    const float* b2    = (const float*)d_in[10];
    const float* Wb1   = (const float*)d_in[11];
    const float* bb1   = (const float*)d_in[12];
    const float* Wb2   = (const float*)d_in[13];
    const float* bb2   = (const float*)d_in[14];

    int B = in_sizes[0] / TOT;
    float* out       = (float*)d_out;
    float* out_state = out;                      // [B, 7]
    float* out_y     = out + (size_t)B * TOT;    // [B, 3]

    int grid = (B + NTHREADS - 1) / NTHREADS;
    phygru_kernel<<<grid, NTHREADS>>>(state, u, A, Bm, C, Wz, bz, W1, b1,
                                      W2, b2, Wb1, bb1, Wb2, bb2,
                                      out_state, out_y, B);
}

// round 2
// speedup vs baseline: 2.2246x; 2.2246x over previous
#include <cuda_runtime.h>

typedef unsigned long long u64;

#define NTHREADS 128

#define SDIM   3
#define LDIM   4
#define IDIM   3
#define TOT    7
#define SUDIM  10
#define HIDL   64
#define HIDB   32
#define DT_F   0.01f

// Duplicated-pair shared layout (float offsets). All row strides are multiples
// of 4 floats (16B) and all bases are 16B-aligned.
#define W1D    0        // 64 rows x 24 floats: [10 w-pairs][b1 pair][pad pair]
#define W2TD   1536     // 64 rows x 8  floats: [4 pairs: W2[0..3][j]]
#define WZD    2048     // 7 rows x 24 floats: [10 w-pairs][bz pair][pad pair]
#define WB1D   2216     // 96 rows x 16 floats: [6 w-pairs][bb1 pair][wb2 pair]
#define PHYSD  3752     // 3 rows x 12 floats: [A row 3 pairs][Bm row 3 pairs]
#define CD     3788     // 3 rows x 8 floats:  [C row 3 pairs][zero pad pair]
#define B2D    3812     // 4 pairs
#define BB2D   3820     // 3 pairs
#define W_TOTAL 3828    // floats (~15.3 KB)

__device__ __forceinline__ u64 pack2(float lo, float hi) {
    u64 r; asm("mov.b64 %0, {%1, %2};" : "=l"(r) : "f"(lo), "f"(hi)); return r;
}
__device__ __forceinline__ void unpack2(u64 v, float& lo, float& hi) {
    asm("mov.b64 {%0, %1}, %2;" : "=f"(lo), "=f"(hi) : "l"(v));
}
__device__ __forceinline__ u64 ffma2(u64 a, u64 b, u64 c) {
    u64 d; asm("fma.rn.f32x2 %0, %1, %2, %3;" : "=l"(d) : "l"(a), "l"(b), "l"(c));
    return d;
}
__device__ __forceinline__ float fast_tanh(float x) {
    float r; asm("tanh.approx.f32 %0, %1;" : "=f"(r) : "f"(x)); return r;
}
__device__ __forceinline__ u64 tanh2(u64 v) {
    float lo, hi; unpack2(v, lo, hi);
    return pack2(fast_tanh(lo), fast_tanh(hi));
}

__global__ void __launch_bounds__(NTHREADS)
phygru_kernel(const float* __restrict__ state,
              const float* __restrict__ u,
              const float* __restrict__ gA,  const float* __restrict__ gBm,
              const float* __restrict__ gC,  const float* __restrict__ gWz,
              const float* __restrict__ gbz, const float* __restrict__ gW1,
              const float* __restrict__ gb1, const float* __restrict__ gW2,
              const float* __restrict__ gb2, const float* __restrict__ gWb1,
              const float* __restrict__ gbb1,const float* __restrict__ gWb2,
              const float* __restrict__ gbb2,
              float* __restrict__ out_state,
              float* __restrict__ out_y,
              int B, int T)   // T = B/4 (stride between row groups)
{
    __shared__ __align__(16) float ws[W_TOTAL];

    // ---- Stage weights as duplicated pairs ----
    // W1D: 64 x 12 pair-slots
    for (int idx = threadIdx.x; idx < 64 * 12; idx += NTHREADS) {
        int r = idx / 12, c = idx % 12;
        float v = (c < 10) ? gW1[r * 10 + c] : (c == 10 ? gb1[r] : 0.0f);
        ws[W1D + r * 24 + 2 * c] = v;
        ws[W1D + r * 24 + 2 * c + 1] = v;
    }
    // W2TD: 64 x 4 pair-slots (transposed W2)
    for (int idx = threadIdx.x; idx < 64 * 4; idx += NTHREADS) {
        int j = idx / 4, o = idx % 4;
        float v = gW2[o * HIDL + j];
        ws[W2TD + j * 8 + 2 * o] = v;
        ws[W2TD + j * 8 + 2 * o + 1] = v;
    }
    // WZD: 7 x 12 pair-slots
    for (int idx = threadIdx.x; idx < 7 * 12; idx += NTHREADS) {
        int r = idx / 12, c = idx % 12;
        float v = (c < 10) ? gWz[r * 10 + c] : (c == 10 ? gbz[r] : 0.0f);
        ws[WZD + r * 24 + 2 * c] = v;
        ws[WZD + r * 24 + 2 * c + 1] = v;
    }
    // WB1D: 96 x 8 pair-slots; r = k*32 + j
    for (int idx = threadIdx.x; idx < 96 * 8; idx += NTHREADS) {
        int r = idx / 8, c = idx % 8;
        float v = (c < 6) ? gWb1[r * 6 + c] : (c == 6 ? gbb1[r] : gWb2[r]);
        ws[WB1D + r * 16 + 2 * c] = v;
        ws[WB1D + r * 16 + 2 * c + 1] = v;
    }
    // small blocks
    for (int idx = threadIdx.x; idx < 3 * 6; idx += NTHREADS) {
        int r = idx / 6, c = idx % 6;
        float v = (c < 3) ? gA[r * 3 + c] : gBm[r * 3 + (c - 3)];
        ws[PHYSD + r * 12 + 2 * c] = v;
        ws[PHYSD + r * 12 + 2 * c + 1] = v;
    }
    for (int idx = threadIdx.x; idx < 3 * 4; idx += NTHREADS) {
        int r = idx / 4, c = idx % 4;
        float v = (c < 3) ? gC[r * 3 + c] : 0.0f;
        ws[CD + r * 8 + 2 * c] = v;
        ws[CD + r * 8 + 2 * c + 1] = v;
    }
    for (int idx = threadIdx.x; idx < 4; idx += NTHREADS) {
        ws[B2D + 2 * idx] = gb2[idx];
        ws[B2D + 2 * idx + 1] = gb2[idx];
    }
    for (int idx = threadIdx.x; idx < 3; idx += NTHREADS) {
        ws[BB2D + 2 * idx] = gbb2[idx];
        ws[BB2D + 2 * idx + 1] = gbb2[idx];
    }
    __syncthreads();

    int t = blockIdx.x * NTHREADS + threadIdx.x;
    if (t >= T) return;
    // 4 rows per thread: (r0,r1) = pair A, (r2,r3) = pair B; all coalesced.
    int r0 = t, r1 = t + T, r2 = t + 2 * T, r3 = t + 3 * T;

    // ---- Load su pairs ----
    u64 suA[SUDIM], suB[SUDIM];
    #pragma unroll
    for (int i = 0; i < TOT; i++) {
        suA[i] = pack2(__ldg(state + (size_t)r0 * TOT + i),
                       __ldg(state + (size_t)r1 * TOT + i));
        suB[i] = pack2(__ldg(state + (size_t)r2 * TOT + i),
                       __ldg(state + (size_t)r3 * TOT + i));
    }
    #pragma unroll
    for (int i = 0; i < IDIM; i++) {
        suA[TOT + i] = pack2(__ldg(u + (size_t)r0 * IDIM + i),
                             __ldg(u + (size_t)r1 * IDIM + i));
        suB[TOT + i] = pack2(__ldg(u + (size_t)r2 * IDIM + i),
                             __ldg(u + (size_t)r3 * IDIM + i));
    }

    const u64 DT2 = pack2(DT_F, DT_F);
    u64 candA[TOT], candB[TOT];

    // ---- Physics: cand[0..2] = s + DT*(A s + Bm u) ----
    {
        const ulonglong2* ph = (const ulonglong2*)(ws + PHYSD);
        #pragma unroll
        for (int i = 0; i < SDIM; i++) {
            ulonglong2 v0 = ph[i * 3 + 0], v1 = ph[i * 3 + 1], v2 = ph[i * 3 + 2];
            u64 dA = 0ull, dB = 0ull;
            dA = ffma2(v0.x, suA[0], dA);  dB = ffma2(v0.x, suB[0], dB);
            dA = ffma2(v0.y, suA[1], dA);  dB = ffma2(v0.y, suB[1], dB);
            dA = ffma2(v1.x, suA[2], dA);  dB = ffma2(v1.x, suB[2], dB);
            dA = ffma2(v1.y, suA[7], dA);  dB = ffma2(v1.y, suB[7], dB);
            dA = ffma2(v2.x, suA[8], dA);  dB = ffma2(v2.x, suB[8], dB);
            dA = ffma2(v2.y, suA[9], dA);  dB = ffma2(v2.y, suB[9], dB);
            candA[i] = ffma2(DT2, dA, suA[i]);
            candB[i] = ffma2(DT2, dB, suB[i]);
        }
    }

    // ---- Latent MLP: acc = b2 + W2 tanh(W1 su + b1); cand[3..6] ----
    {
        const ulonglong2* w1r = (const ulonglong2*)(ws + W1D);
        const ulonglong2* w2r = (const ulonglong2*)(ws + W2TD);
        u64 accA[LDIM], accB[LDIM];
        #pragma unroll
        for (int o = 0; o < LDIM; o++) {
            u64 b = *(const u64*)(ws + B2D + 2 * o);
            accA[o] = b; accB[o] = b;
        }
        #pragma unroll 2
        for (int j = 0; j < HIDL; j++) {
            ulonglong2 q0 = w1r[j * 6 + 0], q1 = w1r[j * 6 + 1];
            ulonglong2 q2 = w1r[j * 6 + 2], q3 = w1r[j * 6 + 3];
            ulonglong2 q4 = w1r[j * 6 + 4], q5 = w1r[j * 6 + 5];
            u64 tA = q5.x, tB = q5.x;
            tA = ffma2(q0.x, suA[0], tA);  tB = ffma2(q0.x, suB[0], tB);
            tA = ffma2(q0.y, suA[1], tA);  tB = ffma2(q0.y, suB[1], tB);
            tA = ffma2(q1.x, suA[2], tA);  tB = ffma2(q1.x, suB[2], tB);
            tA = ffma2(q1.y, suA[3], tA);  tB = ffma2(q1.y, suB[3], tB);
            tA = ffma2(q2.x, suA[4], tA);  tB = ffma2(q2.x, suB[4], tB);
            tA = ffma2(q2.y, suA[5], tA);  tB = ffma2(q2.y, suB[5], tB);
            tA = ffma2(q3.x, suA[6], tA);  tB = ffma2(q3.x, suB[6], tB);
            tA = ffma2(q3.y, suA[7], tA);  tB = ffma2(q3.y, suB[7], tB);
            tA = ffma2(q4.x, suA[8], tA);  tB = ffma2(q4.x, suB[8], tB);
            tA = ffma2(q4.y, suA[9], tA);  tB = ffma2(q4.y, suB[9], tB);
            u64 hA = tanh2(tA), hB = tanh2(tB);
            ulonglong2 p0 = w2r[j * 2 + 0], p1 = w2r[j * 2 + 1];
            accA[0] = ffma2(p0.x, hA, accA[0]);  accB[0] = ffma2(p0.x, hB, accB[0]);
            accA[1] = ffma2(p0.y, hA, accA[1]);  accB[1] = ffma2(p0.y, hB, accB[1]);
            accA[2] = ffma2(p1.x, hA, accA[2]);  accB[2] = ffma2(p1.x, hB, accB[2]);
            accA[3] = ffma2(p1.y, hA, accA[3]);  accB[3] = ffma2(p1.y, hB, accB[3]);
        }
        #pragma unroll
        for (int o = 0; o < LDIM; o++) {
            candA[SDIM + o] = ffma2(DT2, accA[o], suA[SDIM + o]);
            candB[SDIM + o] = ffma2(DT2, accB[o], suB[SDIM + o]);
        }
    }

    // ---- Gate + store next_state ----
    {
        const ulonglong2* wzr = (const ulonglong2*)(ws + WZD);
        #pragma unroll
        for (int i = 0; i < TOT; i++) {
            ulonglong2 q0 = wzr[i * 6 + 0], q1 = wzr[i * 6 + 1];
            ulonglong2 q2 = wzr[i * 6 + 2], q3 = wzr[i * 6 + 3];
            ulonglong2 q4 = wzr[i * 6 + 4], q5 = wzr[i * 6 + 5];
            u64 aA = q5.x, aB = q5.x;
            aA = ffma2(q0.x, suA[0], aA);  aB = ffma2(q0.x, suB[0], aB);
            aA = ffma2(q0.y, suA[1], aA);  aB = ffma2(q0.y, suB[1], aB);
            aA = ffma2(q1.x, suA[2], aA);  aB = ffma2(q1.x, suB[2], aB);
            aA = ffma2(q1.y, suA[3], aA);  aB = ffma2(q1.y, suB[3], aB);
            aA = ffma2(q2.x, suA[4], aA);  aB = ffma2(q2.x, suB[4], aB);
            aA = ffma2(q2.y, suA[5], aA);  aB = ffma2(q2.y, suB[5], aB);
            aA = ffma2(q3.x, suA[6], aA);  aB = ffma2(q3.x, suB[6], aB);
            aA = ffma2(q3.y, suA[7], aA);  aB = ffma2(q3.y, suB[7], aB);
            aA = ffma2(q4.x, suA[8], aA);  aB = ffma2(q4.x, suB[8], aB);
            aA = ffma2(q4.y, suA[9], aA);  aB = ffma2(q4.y, suB[9], aB);

            float a0, a1, a2, a3, c0, c1, c2, c3, s0, s1, s2, s3;
            unpack2(aA, a0, a1);  unpack2(aB, a2, a3);
            unpack2(candA[i], c0, c1);  unpack2(candB[i], c2, c3);
            unpack2(suA[i], s0, s1);  unpack2(suB[i], s2, s3);
            float z0 = fmaf(0.5f, fast_tanh(0.5f * a0), 0.5f);
            float z1 = fmaf(0.5f, fast_tanh(0.5f * a1), 0.5f);
            float z2 = fmaf(0.5f, fast_tanh(0.5f * a2), 0.5f);
            float z3 = fmaf(0.5f, fast_tanh(0.5f * a3), 0.5f);
            out_state[(size_t)r0 * TOT + i] = fmaf(z0, c0 - s0, s0);
            out_state[(size_t)r1 * TOT + i] = fmaf(z1, c1 - s1, s1);
            out_state[(size_t)r2 * TOT + i] = fmaf(z2, c2 - s2, s2);
            out_state[(size_t)r3 * TOT + i] = fmaf(z3, c3 - s3, s3);
        }
    }

    // ---- Residual branches + y_phys + store y ----
    {
        const ulonglong2* wbr = (const ulonglong2*)(ws + WB1D);
        const ulonglong2* cdp = (const ulonglong2*)(ws + CD);
        u64 resA[SDIM], resB[SDIM];
        #pragma unroll
        for (int k = 0; k < SDIM; k++) { resA[k] = 0ull; resB[k] = 0ull; }
        #pragma unroll
        for (int k = 0; k < SDIM; k++) {
            #pragma unroll 4
            for (int j = 0; j < HIDB; j++) {
                int r = k * HIDB + j;
                ulonglong2 v0 = wbr[r * 4 + 0], v1 = wbr[r * 4 + 1];
                ulonglong2 v2 = wbr[r * 4 + 2], v3 = wbr[r * 4 + 3];
                u64 tA = v3.x, tB = v3.x;
                tA = ffma2(v0.x, suA[0], tA);  tB = ffma2(v0.x, suB[0], tB);
                tA = ffma2(v0.y, suA[1], tA);  tB = ffma2(v0.y, suB[1], tB);
                tA = ffma2(v1.x, suA[2], tA);  tB = ffma2(v1.x, suB[2], tB);
                tA = ffma2(v1.y, suA[7], tA);  tB = ffma2(v1.y, suB[7], tB);
                tA = ffma2(v2.x, suA[8], tA);  tB = ffma2(v2.x, suB[8], tB);
                tA = ffma2(v2.y, suA[9], tA);  tB = ffma2(v2.y, suB[9], tB);
                u64 hA = tanh2(tA), hB = tanh2(tB);
                resA[k] = ffma2(v3.y, hA, resA[k]);
                resB[k] = ffma2(v3.y, hB, resB[k]);
            }
        }
        #pragma unroll
        for (int k = 0; k < SDIM; k++) {
            ulonglong2 c0 = cdp[k * 2 + 0], c1 = cdp[k * 2 + 1];
            u64 yA = *(const u64*)(ws + BB2D + 2 * k);
            u64 yB = yA;
            yA = ffma2(c0.x, suA[0], yA);  yB = ffma2(c0.x, suB[0], yB);
            yA = ffma2(c0.y, suA[1], yA);  yB = ffma2(c0.y, suB[1], yB);
            yA = ffma2(c1.x, suA[2], yA);  yB = ffma2(c1.x, suB[2], yB);
            float ya0, ya1, yb0, yb1, ra0, ra1, rb0, rb1;
            unpack2(yA, ya0, ya1);  unpack2(yB, yb0, yb1);
            unpack2(resA[k], ra0, ra1);  unpack2(resB[k], rb0, rb1);
            out_y[(size_t)r0 * SDIM + k] = ya0 + ra0;
            out_y[(size_t)r1 * SDIM + k] = ya1 + ra1;
            out_y[(size_t)r2 * SDIM + k] = yb0 + rb0;
            out_y[(size_t)r3 * SDIM + k] = yb1 + rb1;
        }
    }
}

extern "C" void kernel_launch(void* const* d_in, const int* in_sizes, int n_in,
                              void* d_out, int out_size) {
    const float* state = (const float*)d_in[0];
    const float* u     = (const float*)d_in[1];
    const float* A     = (const float*)d_in[2];
    const float* Bm    = (const float*)d_in[3];
    const float* C     = (const float*)d_in[4];
    const float* Wz    = (const float*)d_in[5];
    const float* bz    = (const float*)d_in[6];
    const float* W1    = (const float*)d_in[7];
    const float* b1    = (const float*)d_in[8];
    const float* W2    = (const float*)d_in[9];
    const float* b2    = (const float*)d_in[10];
    const float* Wb1   = (const float*)d_in[11];
    const float* bb1   = (const float*)d_in[12];
    const float* Wb2   = (const float*)d_in[13];
    const float* bb2   = (const float*)d_in[14];

    int B = in_sizes[0] / TOT;
    int T = B / 4;                       // rows per group (B = 2^21, divisible)
    float* out       = (float*)d_out;
    float* out_state = out;              // [B, 7]
    float* out_y     = out + (size_t)B * TOT;  // [B, 3]

    int grid = (T + NTHREADS - 1) / NTHREADS;
    phygru_kernel<<<grid, NTHREADS>>>(state, u, A, Bm, C, Wz, bz, W1, b1,
                                      W2, b2, Wb1, bb1, Wb2, bb2,
                                      out_state, out_y, B, T);
}